// round 16
// baseline (speedup 1.0000x reference)
#include <cuda_runtime.h>
#include <cuda_bf16.h>
#include <cstdint>

// ---------------- problem-size scratch (device globals; no allocation) ------
#define MAXN 100000
#define MAXE 1000000
#define F 64

__device__ int      g_deg[MAXN];
__device__ int      g_rowptr[MAXN + 1];
__device__ int      g_cursor[MAXN];
__device__ int      g_csr[MAXE];
__device__ int      g_partials[128];
__device__ float    g_dinv[MAXN];
__device__ float    g_X1[MAXN * F];
__device__ float    g_X2[MAXN * F];
__device__ float    g_Y1[MAXN * F];
__device__ float    g_Y2[MAXN * F];
// packed bf16 hi/lo weight planes: L1 @0 (12288 words), L2 @12288, M1 @24576 (4096), M2 @28672 (2048)
__device__ uint32_t g_ws[32768];

// ---------------- helpers ---------------------------------------------------
__device__ __forceinline__ float bf16hi_f(uint32_t bits16) {
    return __uint_as_float(bits16 << 16);
}
__device__ __forceinline__ uint32_t pack2(float even_k, float odd_k,
                                          float* r_even, float* r_odd) {
    uint32_t he = (uint32_t)__bfloat16_as_ushort(__float2bfloat16_rn(even_k));
    uint32_t ho = (uint32_t)__bfloat16_as_ushort(__float2bfloat16_rn(odd_k));
    *r_even = even_k - bf16hi_f(he);
    *r_odd  = odd_k  - bf16hi_f(ho);
    return he | (ho << 16);
}
__device__ __forceinline__ uint32_t pack2lo(float le, float lo) {
    uint32_t a = (uint32_t)__bfloat16_as_ushort(__float2bfloat16_rn(le));
    uint32_t b = (uint32_t)__bfloat16_as_ushort(__float2bfloat16_rn(lo));
    return a | (b << 16);
}

#define MMA_BF16(c, a0, a1, a2, a3, b0, b1)                                     \
    asm volatile(                                                               \
        "mma.sync.aligned.m16n8k16.row.col.f32.bf16.bf16.f32 "                  \
        "{%0,%1,%2,%3}, {%4,%5,%6,%7}, {%8,%9}, {%0,%1,%2,%3};"                 \
        : "+f"((c)[0]), "+f"((c)[1]), "+f"((c)[2]), "+f"((c)[3])                \
        : "r"(a0), "r"(a1), "r"(a2), "r"(a3), "r"(b0), "r"(b1))

// ---------------- CSR build ------------------------------------------------
__global__ void zero_deg_k(int n) {
    int i = blockIdx.x * blockDim.x + threadIdx.x;
    if (i < n) g_deg[i] = 0;
}

__global__ void count_k(const int* __restrict__ dst, int e) {
    int i = blockIdx.x * blockDim.x + threadIdx.x;
    if (i < e) atomicAdd(&g_deg[dst[i]], 1);
}

__global__ void scan1_k(int n) {
    __shared__ int wsum[8];
    int t = threadIdx.x;
    int base = blockIdx.x * 1024 + t * 4;
    int v[4];
    int s = 0;
#pragma unroll
    for (int j = 0; j < 4; j++) {
        int idx = base + j;
        int d = (idx < n) ? g_deg[idx] : 0;
        v[j] = s;
        s += d;
    }
    int lane = t & 31, w = t >> 5;
    int incl = s;
#pragma unroll
    for (int o = 1; o < 32; o <<= 1) {
        int x = __shfl_up_sync(0xffffffffu, incl, o);
        if (lane >= o) incl += x;
    }
    if (lane == 31) wsum[w] = incl;
    __syncthreads();
    if (w == 0) {
        int x = (lane < 8) ? wsum[lane] : 0;
#pragma unroll
        for (int o = 1; o < 8; o <<= 1) {
            int y = __shfl_up_sync(0xffffffffu, x, o);
            if (lane >= o) x += y;
        }
        if (lane < 8) wsum[lane] = x;
    }
    __syncthreads();
    int excl = incl - s + ((w > 0) ? wsum[w - 1] : 0);
#pragma unroll
    for (int j = 0; j < 4; j++) {
        int idx = base + j;
        if (idx < n) g_rowptr[idx] = excl + v[j];
    }
    if (t == 0) g_partials[blockIdx.x] = wsum[7];
}

__global__ void scan2_k(int nb) {
    int t = threadIdx.x;
    int v = (t < nb) ? g_partials[t] : 0;
    int lane = t & 31, w = t >> 5;
    int incl = v;
#pragma unroll
    for (int o = 1; o < 32; o <<= 1) {
        int x = __shfl_up_sync(0xffffffffu, incl, o);
        if (lane >= o) incl += x;
    }
    __shared__ int ws[4];
    if (lane == 31) ws[w] = incl;
    __syncthreads();
    int woff = 0;
    for (int i = 0; i < w; i++) woff += ws[i];
    int excl = incl - v + woff;
    if (t < nb) g_partials[t] = excl;
}

__global__ void scan3_k(int n, int e) {
    int i = blockIdx.x * blockDim.x + threadIdx.x;
    if (i < n) {
        int r = g_rowptr[i] + g_partials[i >> 10];
        g_rowptr[i] = r;
        g_cursor[i] = r;
    }
    if (i == 0) g_rowptr[n] = e;
}

__global__ void fill_k(const int* __restrict__ src, const int* __restrict__ dst, int e) {
    int i = blockIdx.x * blockDim.x + threadIdx.x;
    if (i < e) {
        int p = atomicAdd(&g_cursor[dst[i]], 1);
        g_csr[p] = src[i];
    }
}

__global__ void dinv_k(int n) {
    int i = blockIdx.x * blockDim.x + threadIdx.x;
    if (i < n) {
        int d = g_deg[i];
        g_dinv[i] = rsqrtf((float)(d < 1 ? 1 : d));
    }
}

// ---------------- weight prep: [K][OC] fp32 -> packed bf16 hi/lo planes -----
// word layout per plane: j*(K2*8) + k2*8 + nc   (j = c/8, nc = c%8, k2 = k/2)
__global__ void prep_w_k(const float* __restrict__ W, int K, int OC, uint32_t* __restrict__ out) {
    int K2 = K >> 1;
    int BPLANE = (OC >> 3) * K2 * 8;
    int total = K2 * OC;
    for (int idx = blockIdx.x * blockDim.x + threadIdx.x; idx < total;
         idx += gridDim.x * blockDim.x) {
        int k2 = idx / OC, c = idx % OC;
        float x0 = W[(2 * k2) * OC + c];
        float x1 = W[(2 * k2 + 1) * OC + c];
        float l0, l1;
        uint32_t hw = pack2(x0, x1, &l0, &l1);
        uint32_t lw = pack2lo(l0, l1);
        int w = (c >> 3) * (K2 * 8) + k2 * 8 + (c & 7);
        out[w] = hw;
        out[BPLANE + w] = lw;
    }
}

// ---------------- propagation (unchanged) ----------------------------------
template <bool HASADD>
__global__ __launch_bounds__(256) void prop_k(const float* __restrict__ Xin,
                                              const float* __restrict__ Xadd,
                                              float* __restrict__ Xout,
                                              float scale, float add_scale, int n) {
    int warp = (blockIdx.x * blockDim.x + threadIdx.x) >> 5;
    int lane = threadIdx.x & 31;
    if (warp >= n) return;
    int beg = g_rowptr[warp];
    int end = g_rowptr[warp + 1];
    const float2* Xin2 = reinterpret_cast<const float2*>(Xin);
    float ax = 0.f, ay = 0.f;
    for (int e = beg; e < end; ++e) {
        int s = __ldg(&g_csr[e]);
        float ds = __ldg(&g_dinv[s]);
        float2 v = __ldg(&Xin2[s * 32 + lane]);
        ax += ds * v.x;
        ay += ds * v.y;
    }
    float c = scale * g_dinv[warp];
    float ox = c * ax, oy = c * ay;
    if (HASADD) {
        float2 a = __ldg(&reinterpret_cast<const float2*>(Xadd)[warp * 32 + lane]);
        ox += add_scale * a.x;
        oy += add_scale * a.y;
    }
    float2 o; o.x = ox; o.y = oy;
    reinterpret_cast<float2*>(Xout)[warp * 32 + lane] = o;
}

// ---------------- mma.sync bf16-split GEMM ----------------------------------
// Y[128-row tile, OC] = act([X0|X1|X2] @ W + b).  K = NSEG*64.
// 8 warps, warp w owns rows w*16..w*16+15, all OC columns.
template <int NSEG, int OC, bool RELU>
__global__ __launch_bounds__(256, 2) void mma_gemm_k(const float* __restrict__ X0,
                                                     const float* __restrict__ X1,
                                                     const float* __restrict__ X2,
                                                     const uint32_t* __restrict__ Bpack,
                                                     const float* __restrict__ bias,
                                                     float* __restrict__ Y, int n) {
    constexpr int K2 = NSEG * 32;          // k-pairs total
    constexpr int NT = OC / 8;             // n-tiles
    constexpr int BPLANE = NT * K2 * 8;
    constexpr int BW = 2 * BPLANE;
    constexpr int ASTRIDE = 136;           // words per k2-row (128 + 8 pad)
    constexpr int APLANE = 32 * ASTRIDE;   // one 64-k chunk, one plane

    extern __shared__ uint32_t sm[];
    uint32_t* Bs = sm;
    uint32_t* As = sm + BW;

    int tid = threadIdx.x;
    int wid = tid >> 5;
    int lane = tid & 31;
    int tile0 = blockIdx.x * 128;

    // load packed B once (already in fragment-native layout)
    {
        const uint4* src = reinterpret_cast<const uint4*>(Bpack);
        uint4* dstB = reinterpret_cast<uint4*>(Bs);
        for (int i = tid; i < BW / 4; i += 256) dstB[i] = src[i];
    }

    float acc[NT][4];
#pragma unroll
    for (int j = 0; j < NT; j++)
#pragma unroll
        for (int q = 0; q < 4; q++) acc[j][q] = 0.f;

    const float* xs[3] = {X0, X1, X2};

#pragma unroll
    for (int s = 0; s < NSEG; s++) {
        const float* Xs = xs[s];
        __syncthreads();   // previous chunk consumed / B ready
        // stage A chunk: 128 rows x 64 k -> bf16x2 hi/lo planes
        for (int i = tid; i < 128 * 16; i += 256) {
            int row = i >> 4, c4 = i & 15;
            int gr = tile0 + row;
            float4 v = make_float4(0.f, 0.f, 0.f, 0.f);
            if (gr < n) v = __ldg(reinterpret_cast<const float4*>(Xs + (size_t)gr * 64) + c4);
            float l0, l1, l2, l3;
            uint32_t hw0 = pack2(v.x, v.y, &l0, &l1);
            uint32_t hw1 = pack2(v.z, v.w, &l2, &l3);
            int k2a = c4 * 2;
            As[k2a * ASTRIDE + row]           = hw0;
            As[(k2a + 1) * ASTRIDE + row]     = hw1;
            As[APLANE + k2a * ASTRIDE + row]       = pack2lo(l0, l1);
            As[APLANE + (k2a + 1) * ASTRIDE + row] = pack2lo(l2, l3);
        }
        __syncthreads();

#pragma unroll
        for (int t = 0; t < 4; t++) {
            int k2l = t * 8 + (lane & 3);
            int arow = wid * 16 + (lane >> 2);
            uint32_t ah0 = As[k2l * ASTRIDE + arow];
            uint32_t ah1 = As[k2l * ASTRIDE + arow + 8];
            uint32_t ah2 = As[(k2l + 4) * ASTRIDE + arow];
            uint32_t ah3 = As[(k2l + 4) * ASTRIDE + arow + 8];
            uint32_t al0 = As[APLANE + k2l * ASTRIDE + arow];
            uint32_t al1 = As[APLANE + k2l * ASTRIDE + arow + 8];
            uint32_t al2 = As[APLANE + (k2l + 4) * ASTRIDE + arow];
            uint32_t al3 = As[APLANE + (k2l + 4) * ASTRIDE + arow + 8];

            int bbase = (s * 32 + t * 8 + (lane & 3)) * 8 + (lane >> 2);
#pragma unroll
            for (int j = 0; j < NT; j++) {
                int o = j * (K2 * 8) + bbase;
                uint32_t bh0 = Bs[o];
                uint32_t bh1 = Bs[o + 32];
                uint32_t bl0 = Bs[BPLANE + o];
                uint32_t bl1 = Bs[BPLANE + o + 32];
                MMA_BF16(acc[j], ah0, ah1, ah2, ah3, bh0, bh1);
                MMA_BF16(acc[j], ah0, ah1, ah2, ah3, bl0, bl1);
                MMA_BF16(acc[j], al0, al1, al2, al3, bh0, bh1);
            }
        }
    }

    // epilogue
    int r0 = tile0 + wid * 16 + (lane >> 2);
    int r1 = r0 + 8;
#pragma unroll
    for (int j = 0; j < NT; j++) {
        int col = j * 8 + (lane & 3) * 2;
        float b0 = __ldg(bias + col);
        float b1 = __ldg(bias + col + 1);
        float v0 = acc[j][0] + b0, v1 = acc[j][1] + b1;
        float v2 = acc[j][2] + b0, v3 = acc[j][3] + b1;
        if (RELU) {
            v0 = fmaxf(v0, 0.f); v1 = fmaxf(v1, 0.f);
            v2 = fmaxf(v2, 0.f); v3 = fmaxf(v3, 0.f);
        }
        if (r0 < n) *reinterpret_cast<float2*>(Y + (size_t)r0 * OC + col) = make_float2(v0, v1);
        if (r1 < n) *reinterpret_cast<float2*>(Y + (size_t)r1 * OC + col) = make_float2(v2, v3);
    }
}

// ---------------- launch --------------------------------------------------
extern "C" void kernel_launch(void* const* d_in, const int* in_sizes, int n_in,
                              void* d_out, int out_size) {
    const float* feat = (const float*)d_in[0];
    const int*   src  = (const int*)d_in[1];
    const int*   dst  = (const int*)d_in[2];
    const float* W1  = (const float*)d_in[4];
    const float* b1  = (const float*)d_in[5];
    const float* W2  = (const float*)d_in[6];
    const float* b2  = (const float*)d_in[7];
    const float* Wm1 = (const float*)d_in[8];
    const float* bm1 = (const float*)d_in[9];
    const float* Wm2 = (const float*)d_in[10];
    const float* bm2 = (const float*)d_in[11];
    float* out = (float*)d_out;

    int n = in_sizes[0] / F;
    int e = in_sizes[1];

    float *X1p, *X2p, *Y1p, *Y2p;
    uint32_t* WSp;
    cudaGetSymbolAddress((void**)&X1p, g_X1);
    cudaGetSymbolAddress((void**)&X2p, g_X2);
    cudaGetSymbolAddress((void**)&Y1p, g_Y1);
    cudaGetSymbolAddress((void**)&Y2p, g_Y2);
    cudaGetSymbolAddress((void**)&WSp, g_ws);

    // dynamic smem sizes (bytes)
    const int SM3    = (2 * 8 * 96 * 8 + 2 * 32 * 136) * 4;   // 83968
    const int SM1_64 = (2 * 8 * 32 * 8 + 2 * 32 * 136) * 4;   // 51200
    const int SM1_32 = (2 * 4 * 32 * 8 + 2 * 32 * 136) * 4;   // 43008
    cudaFuncSetAttribute(mma_gemm_k<3, 64, true>,
                         cudaFuncAttributeMaxDynamicSharedMemorySize, SM3);
    cudaFuncSetAttribute(mma_gemm_k<1, 64, true>,
                         cudaFuncAttributeMaxDynamicSharedMemorySize, SM1_64);
    cudaFuncSetAttribute(mma_gemm_k<1, 32, false>,
                         cudaFuncAttributeMaxDynamicSharedMemorySize, SM1_32);

    int nb1024 = (n + 1023) / 1024;
    int nbN = (n + 255) / 256;
    int nbE = (e + 255) / 256;
    int nbProp = (n + 7) / 8;
    int tiles = (n + 127) / 128;

    // --- CSR build + weight prep ---
    zero_deg_k<<<nbN, 256>>>(n);
    count_k<<<nbE, 256>>>(dst, e);
    scan1_k<<<nb1024, 256>>>(n);
    scan2_k<<<1, 128>>>(nb1024);
    scan3_k<<<nbN, 256>>>(n, e);
    fill_k<<<nbE, 256>>>(src, dst, e);
    dinv_k<<<nbN, 256>>>(n);
    prep_w_k<<<24, 256>>>(W1, 192, 64, WSp + 0);
    prep_w_k<<<24, 256>>>(W2, 192, 64, WSp + 12288);
    prep_w_k<<<8, 256>>>(Wm1, 64, 64, WSp + 24576);
    prep_w_k<<<4, 256>>>(Wm2, 64, 32, WSp + 28672);

    // --- ChebConv layer 1 ---
    prop_k<false><<<nbProp, 256>>>(feat, nullptr, X1p, -1.f, 0.f, n);
    prop_k<true><<<nbProp, 256>>>(X1p, feat, X2p, -2.f, -1.f, n);
    mma_gemm_k<3, 64, true><<<tiles, 256, SM3>>>(feat, X1p, X2p, WSp + 0, b1, Y1p, n);

    // --- ChebConv layer 2 ---
    prop_k<false><<<nbProp, 256>>>(Y1p, nullptr, X1p, -1.f, 0.f, n);
    prop_k<true><<<nbProp, 256>>>(X1p, Y1p, X2p, -2.f, -1.f, n);
    mma_gemm_k<3, 64, true><<<tiles, 256, SM3>>>(Y1p, X1p, X2p, WSp + 12288, b2, Y2p, n);

    // --- MLP ---
    mma_gemm_k<1, 64, true><<<tiles, 256, SM1_64>>>(Y2p, nullptr, nullptr, WSp + 24576, bm1, X1p, n);
    mma_gemm_k<1, 32, false><<<tiles, 256, SM1_32>>>(X1p, nullptr, nullptr, WSp + 28672, bm2, out, n);
}

// round 17
// speedup vs baseline: 1.0089x; 1.0089x over previous
#include <cuda_runtime.h>
#include <cuda_bf16.h>
#include <cstdint>

// ---------------- problem-size scratch (device globals; no allocation) ------
#define MAXN 100000
#define MAXE 1000000
#define F 64

__device__ int      g_deg[MAXN];
__device__ int      g_rowptr[MAXN + 1];
__device__ int      g_cursor[MAXN];
__device__ int      g_csr[MAXE];
__device__ int      g_partials[128];
__device__ float    g_dinv[MAXN];
__device__ float    g_X1[MAXN * F];
__device__ float    g_X2[MAXN * F];
__device__ float    g_Y1[MAXN * F];
__device__ float    g_Y2[MAXN * F];
// packed bf16 hi/lo weight planes: L1 @0 (12288 words), L2 @12288, M1 @24576 (4096), M2 @28672 (2048)
__device__ uint32_t g_ws[32768];

// ---------------- helpers ---------------------------------------------------
__device__ __forceinline__ float bf16hi_f(uint32_t bits16) {
    return __uint_as_float(bits16 << 16);
}
__device__ __forceinline__ uint32_t pack2(float even_k, float odd_k,
                                          float* r_even, float* r_odd) {
    uint32_t he = (uint32_t)__bfloat16_as_ushort(__float2bfloat16_rn(even_k));
    uint32_t ho = (uint32_t)__bfloat16_as_ushort(__float2bfloat16_rn(odd_k));
    *r_even = even_k - bf16hi_f(he);
    *r_odd  = odd_k  - bf16hi_f(ho);
    return he | (ho << 16);
}
__device__ __forceinline__ uint32_t pack2lo(float le, float lo) {
    uint32_t a = (uint32_t)__bfloat16_as_ushort(__float2bfloat16_rn(le));
    uint32_t b = (uint32_t)__bfloat16_as_ushort(__float2bfloat16_rn(lo));
    return a | (b << 16);
}

#define MMA_BF16(c, a0, a1, a2, a3, b0, b1)                                     \
    asm volatile(                                                               \
        "mma.sync.aligned.m16n8k16.row.col.f32.bf16.bf16.f32 "                  \
        "{%0,%1,%2,%3}, {%4,%5,%6,%7}, {%8,%9}, {%0,%1,%2,%3};"                 \
        : "+f"((c)[0]), "+f"((c)[1]), "+f"((c)[2]), "+f"((c)[3])                \
        : "r"(a0), "r"(a1), "r"(a2), "r"(a3), "r"(b0), "r"(b1))

// ---------------- CSR build ------------------------------------------------
__global__ void zero_deg_k(int n) {
    int i = blockIdx.x * blockDim.x + threadIdx.x;
    if (i < n) g_deg[i] = 0;
}

__global__ void count_k(const int* __restrict__ dst, int e) {
    int i = blockIdx.x * blockDim.x + threadIdx.x;
    if (i < e) atomicAdd(&g_deg[dst[i]], 1);
}

__global__ void scan1_k(int n) {
    __shared__ int wsum[8];
    int t = threadIdx.x;
    int base = blockIdx.x * 1024 + t * 4;
    int v[4];
    int s = 0;
#pragma unroll
    for (int j = 0; j < 4; j++) {
        int idx = base + j;
        int d = (idx < n) ? g_deg[idx] : 0;
        v[j] = s;
        s += d;
    }
    int lane = t & 31, w = t >> 5;
    int incl = s;
#pragma unroll
    for (int o = 1; o < 32; o <<= 1) {
        int x = __shfl_up_sync(0xffffffffu, incl, o);
        if (lane >= o) incl += x;
    }
    if (lane == 31) wsum[w] = incl;
    __syncthreads();
    if (w == 0) {
        int x = (lane < 8) ? wsum[lane] : 0;
#pragma unroll
        for (int o = 1; o < 8; o <<= 1) {
            int y = __shfl_up_sync(0xffffffffu, x, o);
            if (lane >= o) x += y;
        }
        if (lane < 8) wsum[lane] = x;
    }
    __syncthreads();
    int excl = incl - s + ((w > 0) ? wsum[w - 1] : 0);
#pragma unroll
    for (int j = 0; j < 4; j++) {
        int idx = base + j;
        if (idx < n) g_rowptr[idx] = excl + v[j];
    }
    if (t == 0) g_partials[blockIdx.x] = wsum[7];
}

__global__ void scan2_k(int nb) {
    int t = threadIdx.x;
    int v = (t < nb) ? g_partials[t] : 0;
    int lane = t & 31, w = t >> 5;
    int incl = v;
#pragma unroll
    for (int o = 1; o < 32; o <<= 1) {
        int x = __shfl_up_sync(0xffffffffu, incl, o);
        if (lane >= o) incl += x;
    }
    __shared__ int ws[4];
    if (lane == 31) ws[w] = incl;
    __syncthreads();
    int woff = 0;
    for (int i = 0; i < w; i++) woff += ws[i];
    int excl = incl - v + woff;
    if (t < nb) g_partials[t] = excl;
}

__global__ void scan3_k(int n, int e) {
    int i = blockIdx.x * blockDim.x + threadIdx.x;
    if (i < n) {
        int r = g_rowptr[i] + g_partials[i >> 10];
        g_rowptr[i] = r;
        g_cursor[i] = r;
    }
    if (i == 0) g_rowptr[n] = e;
}

__global__ void fill_k(const int* __restrict__ src, const int* __restrict__ dst, int e) {
    int i = blockIdx.x * blockDim.x + threadIdx.x;
    if (i < e) {
        int p = atomicAdd(&g_cursor[dst[i]], 1);
        g_csr[p] = src[i];
    }
}

__global__ void dinv_k(int n) {
    int i = blockIdx.x * blockDim.x + threadIdx.x;
    if (i < n) {
        int d = g_deg[i];
        g_dinv[i] = rsqrtf((float)(d < 1 ? 1 : d));
    }
}

// ---------------- weight prep: [K][OC] fp32 -> packed bf16 hi/lo planes -----
// word layout per plane: j*(K2*8) + k2*8 + nc   (j = c/8, nc = c%8, k2 = k/2)
__global__ void prep_w_k(const float* __restrict__ W, int K, int OC, uint32_t* __restrict__ out) {
    int K2 = K >> 1;
    int BPLANE = (OC >> 3) * K2 * 8;
    int total = K2 * OC;
    for (int idx = blockIdx.x * blockDim.x + threadIdx.x; idx < total;
         idx += gridDim.x * blockDim.x) {
        int k2 = idx / OC, c = idx % OC;
        float x0 = W[(2 * k2) * OC + c];
        float x1 = W[(2 * k2 + 1) * OC + c];
        float l0, l1;
        uint32_t hw = pack2(x0, x1, &l0, &l1);
        uint32_t lw = pack2lo(l0, l1);
        int w = (c >> 3) * (K2 * 8) + k2 * 8 + (c & 7);
        out[w] = hw;
        out[BPLANE + w] = lw;
    }
}

// ---------------- propagation (unchanged) ----------------------------------
template <bool HASADD>
__global__ __launch_bounds__(256) void prop_k(const float* __restrict__ Xin,
                                              const float* __restrict__ Xadd,
                                              float* __restrict__ Xout,
                                              float scale, float add_scale, int n) {
    int warp = (blockIdx.x * blockDim.x + threadIdx.x) >> 5;
    int lane = threadIdx.x & 31;
    if (warp >= n) return;
    int beg = g_rowptr[warp];
    int end = g_rowptr[warp + 1];
    const float2* Xin2 = reinterpret_cast<const float2*>(Xin);
    float ax = 0.f, ay = 0.f;
    for (int e = beg; e < end; ++e) {
        int s = __ldg(&g_csr[e]);
        float ds = __ldg(&g_dinv[s]);
        float2 v = __ldg(&Xin2[s * 32 + lane]);
        ax += ds * v.x;
        ay += ds * v.y;
    }
    float c = scale * g_dinv[warp];
    float ox = c * ax, oy = c * ay;
    if (HASADD) {
        float2 a = __ldg(&reinterpret_cast<const float2*>(Xadd)[warp * 32 + lane]);
        ox += add_scale * a.x;
        oy += add_scale * a.y;
    }
    float2 o; o.x = ox; o.y = oy;
    reinterpret_cast<float2*>(Xout)[warp * 32 + lane] = o;
}

// ---------------- mma.sync bf16-split GEMM ----------------------------------
// Y[128-row tile, OC] = act([X0|X1|X2] @ W + b).  K = NSEG*64.
// 8 warps, warp w owns rows w*16..w*16+15, all OC columns.
template <int NSEG, int OC, bool RELU>
__global__ __launch_bounds__(256, 2) void mma_gemm_k(const float* __restrict__ X0,
                                                     const float* __restrict__ X1,
                                                     const float* __restrict__ X2,
                                                     const uint32_t* __restrict__ Bpack,
                                                     const float* __restrict__ bias,
                                                     float* __restrict__ Y, int n) {
    constexpr int K2 = NSEG * 32;          // k-pairs total
    constexpr int NT = OC / 8;             // n-tiles
    constexpr int BPLANE = NT * K2 * 8;
    constexpr int BW = 2 * BPLANE;
    constexpr int ASTRIDE = 136;           // words per k2-row (128 + 8 pad)
    constexpr int APLANE = 32 * ASTRIDE;   // one 64-k chunk, one plane

    extern __shared__ uint32_t sm[];
    uint32_t* Bs = sm;
    uint32_t* As = sm + BW;

    int tid = threadIdx.x;
    int wid = tid >> 5;
    int lane = tid & 31;
    int tile0 = blockIdx.x * 128;

    // load packed B once (already in fragment-native layout)
    {
        const uint4* src = reinterpret_cast<const uint4*>(Bpack);
        uint4* dstB = reinterpret_cast<uint4*>(Bs);
        for (int i = tid; i < BW / 4; i += 256) dstB[i] = src[i];
    }

    float acc[NT][4];
#pragma unroll
    for (int j = 0; j < NT; j++)
#pragma unroll
        for (int q = 0; q < 4; q++) acc[j][q] = 0.f;

    const float* xs[3] = {X0, X1, X2};

#pragma unroll
    for (int s = 0; s < NSEG; s++) {
        const float* Xs = xs[s];
        __syncthreads();   // previous chunk consumed / B ready
        // stage A chunk: 128 rows x 64 k -> bf16x2 hi/lo planes
        for (int i = tid; i < 128 * 16; i += 256) {
            int row = i >> 4, c4 = i & 15;
            int gr = tile0 + row;
            float4 v = make_float4(0.f, 0.f, 0.f, 0.f);
            if (gr < n) v = __ldg(reinterpret_cast<const float4*>(Xs + (size_t)gr * 64) + c4);
            float l0, l1, l2, l3;
            uint32_t hw0 = pack2(v.x, v.y, &l0, &l1);
            uint32_t hw1 = pack2(v.z, v.w, &l2, &l3);
            int k2a = c4 * 2;
            As[k2a * ASTRIDE + row]           = hw0;
            As[(k2a + 1) * ASTRIDE + row]     = hw1;
            As[APLANE + k2a * ASTRIDE + row]       = pack2lo(l0, l1);
            As[APLANE + (k2a + 1) * ASTRIDE + row] = pack2lo(l2, l3);
        }
        __syncthreads();

#pragma unroll
        for (int t = 0; t < 4; t++) {
            int k2l = t * 8 + (lane & 3);
            int arow = wid * 16 + (lane >> 2);
            uint32_t ah0 = As[k2l * ASTRIDE + arow];
            uint32_t ah1 = As[k2l * ASTRIDE + arow + 8];
            uint32_t ah2 = As[(k2l + 4) * ASTRIDE + arow];
            uint32_t ah3 = As[(k2l + 4) * ASTRIDE + arow + 8];
            uint32_t al0 = As[APLANE + k2l * ASTRIDE + arow];
            uint32_t al1 = As[APLANE + k2l * ASTRIDE + arow + 8];
            uint32_t al2 = As[APLANE + (k2l + 4) * ASTRIDE + arow];
            uint32_t al3 = As[APLANE + (k2l + 4) * ASTRIDE + arow + 8];

            int bbase = (s * 32 + t * 8 + (lane & 3)) * 8 + (lane >> 2);
#pragma unroll
            for (int j = 0; j < NT; j++) {
                int o = j * (K2 * 8) + bbase;
                uint32_t bh0 = Bs[o];
                uint32_t bh1 = Bs[o + 32];
                uint32_t bl0 = Bs[BPLANE + o];
                uint32_t bl1 = Bs[BPLANE + o + 32];
                MMA_BF16(acc[j], ah0, ah1, ah2, ah3, bh0, bh1);
                MMA_BF16(acc[j], ah0, ah1, ah2, ah3, bl0, bl1);
                MMA_BF16(acc[j], al0, al1, al2, al3, bh0, bh1);
            }
        }
    }

    // epilogue
    int r0 = tile0 + wid * 16 + (lane >> 2);
    int r1 = r0 + 8;
#pragma unroll
    for (int j = 0; j < NT; j++) {
        int col = j * 8 + (lane & 3) * 2;
        float b0 = __ldg(bias + col);
        float b1 = __ldg(bias + col + 1);
        float v0 = acc[j][0] + b0, v1 = acc[j][1] + b1;
        float v2 = acc[j][2] + b0, v3 = acc[j][3] + b1;
        if (RELU) {
            v0 = fmaxf(v0, 0.f); v1 = fmaxf(v1, 0.f);
            v2 = fmaxf(v2, 0.f); v3 = fmaxf(v3, 0.f);
        }
        if (r0 < n) *reinterpret_cast<float2*>(Y + (size_t)r0 * OC + col) = make_float2(v0, v1);
        if (r1 < n) *reinterpret_cast<float2*>(Y + (size_t)r1 * OC + col) = make_float2(v2, v3);
    }
}

// ---------------- launch --------------------------------------------------
extern "C" void kernel_launch(void* const* d_in, const int* in_sizes, int n_in,
                              void* d_out, int out_size) {
    const float* feat = (const float*)d_in[0];
    const int*   src  = (const int*)d_in[1];
    const int*   dst  = (const int*)d_in[2];
    const float* W1  = (const float*)d_in[4];
    const float* b1  = (const float*)d_in[5];
    const float* W2  = (const float*)d_in[6];
    const float* b2  = (const float*)d_in[7];
    const float* Wm1 = (const float*)d_in[8];
    const float* bm1 = (const float*)d_in[9];
    const float* Wm2 = (const float*)d_in[10];
    const float* bm2 = (const float*)d_in[11];
    float* out = (float*)d_out;

    int n = in_sizes[0] / F;
    int e = in_sizes[1];

    float *X1p, *X2p, *Y1p, *Y2p;
    uint32_t* WSp;
    cudaGetSymbolAddress((void**)&X1p, g_X1);
    cudaGetSymbolAddress((void**)&X2p, g_X2);
    cudaGetSymbolAddress((void**)&Y1p, g_Y1);
    cudaGetSymbolAddress((void**)&Y2p, g_Y2);
    cudaGetSymbolAddress((void**)&WSp, g_ws);

    // dynamic smem sizes (bytes)
    const int SM3    = (2 * 8 * 96 * 8 + 2 * 32 * 136) * 4;   // 83968
    const int SM1_64 = (2 * 8 * 32 * 8 + 2 * 32 * 136) * 4;   // 51200
    const int SM1_32 = (2 * 4 * 32 * 8 + 2 * 32 * 136) * 4;   // 43008
    cudaFuncSetAttribute(mma_gemm_k<3, 64, true>,
                         cudaFuncAttributeMaxDynamicSharedMemorySize, SM3);
    cudaFuncSetAttribute(mma_gemm_k<1, 64, true>,
                         cudaFuncAttributeMaxDynamicSharedMemorySize, SM1_64);
    cudaFuncSetAttribute(mma_gemm_k<1, 32, false>,
                         cudaFuncAttributeMaxDynamicSharedMemorySize, SM1_32);

    int nb1024 = (n + 1023) / 1024;
    int nbN = (n + 255) / 256;
    int nbE = (e + 255) / 256;
    int nbProp = (n + 7) / 8;
    int tiles = (n + 127) / 128;

    // --- CSR build + weight prep ---
    zero_deg_k<<<nbN, 256>>>(n);
    count_k<<<nbE, 256>>>(dst, e);
    scan1_k<<<nb1024, 256>>>(n);
    scan2_k<<<1, 128>>>(nb1024);
    scan3_k<<<nbN, 256>>>(n, e);
    fill_k<<<nbE, 256>>>(src, dst, e);
    dinv_k<<<nbN, 256>>>(n);
    prep_w_k<<<24, 256>>>(W1, 192, 64, WSp + 0);
    prep_w_k<<<24, 256>>>(W2, 192, 64, WSp + 12288);
    prep_w_k<<<8, 256>>>(Wm1, 64, 64, WSp + 24576);
    prep_w_k<<<4, 256>>>(Wm2, 64, 32, WSp + 28672);

    // --- ChebConv layer 1 ---
    prop_k<false><<<nbProp, 256>>>(feat, nullptr, X1p, -1.f, 0.f, n);
    prop_k<true><<<nbProp, 256>>>(X1p, feat, X2p, -2.f, -1.f, n);
    mma_gemm_k<3, 64, true><<<tiles, 256, SM3>>>(feat, X1p, X2p, WSp + 0, b1, Y1p, n);

    // --- ChebConv layer 2 ---
    prop_k<false><<<nbProp, 256>>>(Y1p, nullptr, X1p, -1.f, 0.f, n);
    prop_k<true><<<nbProp, 256>>>(X1p, Y1p, X2p, -2.f, -1.f, n);
    mma_gemm_k<3, 64, true><<<tiles, 256, SM3>>>(Y1p, X1p, X2p, WSp + 12288, b2, Y2p, n);

    // --- MLP ---
    mma_gemm_k<1, 64, true><<<tiles, 256, SM1_64>>>(Y2p, nullptr, nullptr, WSp + 24576, bm1, X1p, n);
    mma_gemm_k<1, 32, false><<<tiles, 256, SM1_32>>>(X1p, nullptr, nullptr, WSp + 28672, bm2, out, n);
}